// round 8
// baseline (speedup 1.0000x reference)
#include <cuda_runtime.h>
#include <cuda_bf16.h>

// DetectionLoss, single fused kernel, v6.
// 96 blocks x 128 threads (single wave on 148 SMs). Each block processes two
// (batch, scale) items, one per 64-thread warp-pair. Sparse evaluation with
// register-resident collision scan. Partials accumulated via fire-and-forget
// REDG atomics into 12 global sums; 96-arrival root counter; thread-0
// finalize reads just 12 floats.

#define NCH   11
#define NCLS  6
#define NT    60
#define NB    64
#define NITEM 192          // 64 batches x 3 scales
#define NBLK  96

__device__ float    g_sum[12];     // [scale*4 + {cls,iou,inner,np}]
__device__ unsigned g_done;

__device__ __forceinline__ float iou_scaled(
    float px, float py, float pw, float ph,
    float tx, float ty, float tw, float th, float sc)
{
    float pw2 = pw * sc * 0.5f, ph2 = ph * sc * 0.5f;
    float tw2 = tw * sc * 0.5f, th2 = th * sc * 0.5f;
    float x11 = px - pw2, x12 = px + pw2;
    float y11 = py - ph2, y12 = py + ph2;
    float x21 = tx - tw2, x22 = tx + tw2;
    float y21 = ty - th2, y22 = ty + th2;
    float iw = fmaxf(fminf(x12, x22) - fmaxf(x11, x21), 0.0f);
    float ih = fmaxf(fminf(y12, y22) - fmaxf(y11, y21), 0.0f);
    float inter = iw * ih;
    float a1 = (x12 - x11) * (y12 - y11);
    float a2 = (x22 - x21) * (y22 - y21);
    return inter / (a1 + a2 - inter + 1e-7f);
}

__global__ void __launch_bounds__(128, 8) dl_fused_kernel(
    const float* __restrict__ p3,
    const float* __restrict__ p4,
    const float* __restrict__ p5,
    const int*   __restrict__ tcls,
    const float* __restrict__ tbox,
    float*       __restrict__ out)
{
    const int t    = threadIdx.x;
    const int half = t >> 6;                    // which item in this block
    const int tid  = t & 63;                    // lane within item group
    const int id   = blockIdx.x * 2 + half;     // 0..191
    const int s    = id >> 6;                   // scale 0..2
    const int b    = id & 63;                   // batch

    const float* pred;
    int W;
    if      (s == 0) { pred = p3; W = 160; }
    else if (s == 1) { pred = p4; W = 80;  }
    else             { pred = p5; W = 40;  }

    __shared__ int4  s_pk4[2][15];   // packed (cell<<6)|cls per item
    __shared__ float s_red[2][2][4]; // [item][warp-in-item][metric]

    float tx = 0.f, ty = 0.f, tw = 0.f, th = 0.f;
    int   cell = -1;
    float z[NCLS], px = 0.f, py = 0.f, pw = 0.f, ph = 0.f;

    if (tid < NT) {
        int   cls = tcls[b * NT + tid];
        float4 bx = reinterpret_cast<const float4*>(tbox)[b * NT + tid];
        tx = bx.x; ty = bx.y; tw = bx.z; th = bx.w;
        int gx = (int)(tx * (float)W); gx = min(max(gx, 0), W - 1);
        int gy = (int)(ty * (float)W); gy = min(max(gy, 0), W - 1);
        cell = gy * W + gx;
        reinterpret_cast<int*>(&s_pk4[half][0])[tid] = (cell << 6) | cls;

        // All 10 scattered pred loads issued up front (MLP=10, overlap scan).
        // 32-bit offsets: max index < 2^25.
        const int HW = W * W;
        const float* base = pred + b * NCH * HW + cell;
        #pragma unroll
        for (int c = 0; c < NCLS; ++c) z[c] = __ldg(base + c * HW);
        px = __ldg(base + 7  * HW);
        py = __ldg(base + 8  * HW);
        pw = __ldg(base + 9  * HW);
        ph = __ldg(base + 10 * HW);
    }
    __syncthreads();

    float cls_p = 0.0f, iou_p = 0.0f, inner_p = 0.0f, np = 0.0f;

    if (tid < NT) {
        // Register-resident scan over this item's 60 packed entries
        // (broadcast LDS.128, conflict-free).
        const int cellsh = cell << 6;
        unsigned cm  = 0u;   // union of one-hot classes at this cell
        int      bad = 0;    // some later target claims this cell
        #pragma unroll
        for (int i = 0; i < 15; ++i) {
            int4 q = s_pk4[half][i];
            int idx = i * 4;
            if (((q.x ^ cellsh) & ~63) == 0) { cm |= 1u << (q.x & 63); bad |= (idx + 0 > tid); }
            if (((q.y ^ cellsh) & ~63) == 0) { cm |= 1u << (q.y & 63); bad |= (idx + 1 > tid); }
            if (((q.z ^ cellsh) & ~63) == 0) { cm |= 1u << (q.z & 63); bad |= (idx + 2 > tid); }
            if (((q.w ^ cellsh) & ~63) == 0) { cm |= 1u << (q.w & 63); bad |= (idx + 3 > tid); }
        }

        if (!bad) {   // owner = last target mapping to this cell
            float bce = 0.0f;
            #pragma unroll
            for (int c = 0; c < NCLS; ++c) {
                float tt = ((cm >> c) & 1u) ? 1.0f : 0.0f;
                bce += fmaxf(z[c], 0.0f) - z[c] * tt
                     + __logf(1.0f + __expf(-fabsf(z[c])));
            }
            float iou   = iou_scaled(px, py, pw, ph, tx, ty, tw, th, 1.0f);
            float inner = iou_scaled(px, py, pw, ph, tx, ty, tw, th, 0.7f);
            cls_p = bce;  iou_p = 1.0f - iou;  inner_p = 1.0f - inner;  np = 1.0f;
        }
    }

    // Warp shfl reduce, then combine the item's 2 warps.
    #pragma unroll
    for (int o = 16; o > 0; o >>= 1) {
        cls_p   += __shfl_down_sync(0xffffffffu, cls_p,   o);
        iou_p   += __shfl_down_sync(0xffffffffu, iou_p,   o);
        inner_p += __shfl_down_sync(0xffffffffu, inner_p, o);
        np      += __shfl_down_sync(0xffffffffu, np,      o);
    }
    const int wInI = tid >> 5;   // warp within item (0/1)
    if ((tid & 31) == 0) {
        s_red[half][wInI][0] = cls_p;  s_red[half][wInI][1] = iou_p;
        s_red[half][wInI][2] = inner_p; s_red[half][wInI][3] = np;
    }
    __syncthreads();

    // Item leaders (t==0, t==64): fire-and-forget REDG into the 12 global
    // sums, then fence so the REDGs are globally visible before this block's
    // counter bump (fence-before-sync / counter-after-sync ordering).
    if (tid == 0) {
        #pragma unroll
        for (int k = 0; k < 4; ++k)
            atomicAdd(&g_sum[s * 4 + k], s_red[half][0][k] + s_red[half][1][k]);
        __threadfence();
    }
    __syncthreads();

    if (t == 0) {
        unsigned d = atomicAdd(&g_done, 1u);
        if (d == NBLK - 1) {
            // All blocks' REDGs are fenced before their counter bumps; we saw
            // the final count, so L2 holds the complete sums.
            float m[12];
            #pragma unroll
            for (int k = 0; k < 12; ++k)
                m[k] = ((const volatile float*)g_sum)[k];

            float cls_total = 0.0f, box_total = 0.0f;
            #pragma unroll
            for (int k2 = 0; k2 < 3; ++k2) {
                float inv = 1.0f / (m[k2 * 4 + 3] + 1e-8f);
                cls_total += m[k2 * 4 + 0] * inv;
                // box = 0.5*iou + 0.5*(0.5*iou + 0.5*inner)
                box_total += 0.75f * (m[k2 * 4 + 1] * inv)
                           + 0.25f * (m[k2 * 4 + 2] * inv);
            }
            cls_total *= (1.0f / 3.0f);
            box_total *= (1.0f / 3.0f);
            out[0] = 0.5f * cls_total + 7.5f * box_total;  // CLS_W, BOX_W
            out[1] = cls_total;
            out[2] = box_total;

            // Reset for the next graph replay (kernel-end membar publishes).
            #pragma unroll
            for (int k = 0; k < 12; ++k) g_sum[k] = 0.0f;
            g_done = 0u;
        }
    }
}

extern "C" void kernel_launch(void* const* d_in, const int* in_sizes, int n_in,
                              void* d_out, int out_size)
{
    const float* p3   = (const float*)d_in[0];
    const float* p4   = (const float*)d_in[1];
    const float* p5   = (const float*)d_in[2];
    const int*   tcls = (const int*)  d_in[3];
    const float* tbox = (const float*)d_in[4];
    float*       out  = (float*)d_out;

    dl_fused_kernel<<<NBLK, 128>>>(p3, p4, p5, tcls, tbox, out);
}